// round 1
// baseline (speedup 1.0000x reference)
#include <cuda_runtime.h>

#define NL 4
#define H 32
#define TT 64
#define NPAIR 4            // f32x2 pairs per warp -> 8 batch per warp
#define BPW (NPAIR * 2)
#define WARPS_CTA 4
#define THREADS (WARPS_CTA * 32)

typedef unsigned long long u64;

// Pre-transposed weights: [k][j] -> float4 of (i,f,g,o) gate weights.
__device__ float4 g_Whh[NL][H][H];
__device__ float4 g_Wih[NL - 1][H][H];
__device__ float4 g_Wih0[2][H];
__device__ float4 g_bias[NL][H];
__device__ float  g_Wlin[H];
__device__ float  g_blin;

__device__ __forceinline__ u64 pk2(float a, float b) {
    u64 r; asm("mov.b64 %0, {%1, %2};" : "=l"(r) : "f"(a), "f"(b)); return r;
}
__device__ __forceinline__ u64 pk2(float a) { return pk2(a, a); }
__device__ __forceinline__ float2 upk(u64 v) {
    float2 r; asm("mov.b64 {%0, %1}, %2;" : "=f"(r.x), "=f"(r.y) : "l"(v)); return r;
}
// Packed fp32x2 FMA (Blackwell): d = a*b + c on both lanes.
__device__ __forceinline__ u64 ffma2(u64 a, u64 b, u64 c) {
    u64 d; asm("fma.rn.f32x2 %0, %1, %2, %3;" : "=l"(d) : "l"(a), "l"(b), "l"(c)); return d;
}

__device__ __forceinline__ float sigm(float v) {
    return __fdividef(1.0f, 1.0f + __expf(-v));
}
__device__ __forceinline__ float tanh_(float v) {
    return __fdividef(2.0f, 1.0f + __expf(-2.0f * v)) - 1.0f;
}

// Accumulate gates += W[k][j](4 gates) * src[p][k] over k=0..31 for 4 pairs.
// wbase = &W[l][0][j] (stride H float4 per k); src = &h_stage[...][p=0][k=0] (u64 view).
__device__ __forceinline__ void mat_acc(const float4* __restrict__ wbase,
                                        const u64* __restrict__ src,
                                        u64* ai, u64* af, u64* ag, u64* ao) {
#pragma unroll 4
    for (int k = 0; k < H; ++k) {
        float4 w = wbase[k * H];
        u64 wi = pk2(w.x), wf = pk2(w.y), wg = pk2(w.z), wo = pk2(w.w);
#pragma unroll
        for (int p = 0; p < NPAIR; ++p) {
            u64 v = src[p * H + k];
            ai[p] = ffma2(v, wi, ai[p]);
            af[p] = ffma2(v, wf, af[p]);
            ag[p] = ffma2(v, wg, ag[p]);
            ao[p] = ffma2(v, wo, ao[p]);
        }
    }
}

__device__ __forceinline__ void cell_update(const u64* ai, const u64* af,
                                            const u64* ag, const u64* ao,
                                            float4 bs, float2* cst,
                                            float2* hdst /* stride H */) {
#pragma unroll
    for (int p = 0; p < NPAIR; ++p) {
        float2 iv = upk(ai[p]), fv = upk(af[p]), gv = upk(ag[p]), ov = upk(ao[p]);
        float i0 = sigm(iv.x + bs.x), i1 = sigm(iv.y + bs.x);
        float f0 = sigm(fv.x + bs.y), f1 = sigm(fv.y + bs.y);
        float g0 = tanh_(gv.x + bs.z), g1 = tanh_(gv.y + bs.z);
        float o0 = sigm(ov.x + bs.w), o1 = sigm(ov.y + bs.w);
        float c0 = f0 * cst[p].x + i0 * g0;
        float c1 = f1 * cst[p].y + i1 * g1;
        cst[p] = make_float2(c0, c1);
        hdst[p * H] = make_float2(o0 * tanh_(c0), o1 * tanh_(c1));
    }
}

__global__ void prep_kernel(const float* __restrict__ W_ih0, const float* __restrict__ W_ih,
                            const float* __restrict__ W_hh, const float* __restrict__ b_ih,
                            const float* __restrict__ b_hh, const float* __restrict__ W_lin,
                            const float* __restrict__ b_lin) {
    int i = blockIdx.x * blockDim.x + threadIdx.x;
    // g_Whh[l][k][j].g <- W_hh[l][g*32+j][k]   (4*32*32*4 = 16384 floats)
    if (i < NL * H * H * 4) {
        int g = i & 3, j = (i >> 2) & 31, k = (i >> 7) & 31, l = i >> 12;
        ((float*)g_Whh)[i] = W_hh[l * 4096 + (g * 32 + j) * 32 + k];
    }
    if (i < (NL - 1) * H * H * 4) {
        int g = i & 3, j = (i >> 2) & 31, k = (i >> 7) & 31, l = i >> 12;
        ((float*)g_Wih)[i] = W_ih[l * 4096 + (g * 32 + j) * 32 + k];
    }
    if (i < 2 * H * 4) {
        int g = i & 3, j = (i >> 2) & 31, k = i >> 7;
        ((float*)g_Wih0)[i] = W_ih0[(g * 32 + j) * 2 + k];
    }
    if (i < NL * H * 4) {
        int g = i & 3, j = (i >> 2) & 31, l = i >> 7;
        ((float*)g_bias)[i] = b_ih[l * 128 + g * 32 + j] + b_hh[l * 128 + g * 32 + j];
    }
    if (i < H) g_Wlin[i] = W_lin[i];
    if (i == 0) g_blin = b_lin[0];
}

__global__ void __launch_bounds__(THREADS)
lstm_kernel(const float* __restrict__ x, float* __restrict__ out) {
    __shared__ float2 h_stage[WARPS_CTA][NL][NPAIR][H];
    const int wid = threadIdx.x >> 5;
    const int j = threadIdx.x & 31;
    const int base = (blockIdx.x * WARPS_CTA + wid) * BPW;

    u64* hs = reinterpret_cast<u64*>(&h_stage[wid][0][0][0]);

#pragma unroll
    for (int l = 0; l < NL; ++l)
#pragma unroll
        for (int p = 0; p < NPAIR; ++p)
            h_stage[wid][l][p][j] = make_float2(0.f, 0.f);

    float2 cst[NL][NPAIR];
#pragma unroll
    for (int l = 0; l < NL; ++l)
#pragma unroll
        for (int p = 0; p < NPAIR; ++p) cst[l][p] = make_float2(0.f, 0.f);

    float4 bs[NL];
#pragma unroll
    for (int l = 0; l < NL; ++l) bs[l] = g_bias[l][j];

    __syncwarp();

    for (int t = 0; t < TT; ++t) {
        // layer-0 inputs: x[b][0][t], x[b][1][t] packed across batch pairs
        u64 xv0[NPAIR], xv1[NPAIR];
#pragma unroll
        for (int p = 0; p < NPAIR; ++p) {
            const float* xb = x + (size_t)(base + 2 * p) * 192 + t;
            xv0[p] = pk2(xb[0], xb[192]);
            xv1[p] = pk2(xb[64], xb[256]);
        }

        u64 ai[NPAIR], af[NPAIR], ag[NPAIR], ao[NPAIR];

        // ---------------- layer 0 ----------------
#pragma unroll
        for (int p = 0; p < NPAIR; ++p) { ai[p] = af[p] = ag[p] = ao[p] = 0ull; }
        {
            float4 w0 = g_Wih0[0][j];
            float4 w1 = g_Wih0[1][j];
            u64 wi0 = pk2(w0.x), wf0 = pk2(w0.y), wg0 = pk2(w0.z), wo0 = pk2(w0.w);
            u64 wi1 = pk2(w1.x), wf1 = pk2(w1.y), wg1 = pk2(w1.z), wo1 = pk2(w1.w);
#pragma unroll
            for (int p = 0; p < NPAIR; ++p) {
                ai[p] = ffma2(xv0[p], wi0, ai[p]);
                af[p] = ffma2(xv0[p], wf0, af[p]);
                ag[p] = ffma2(xv0[p], wg0, ag[p]);
                ao[p] = ffma2(xv0[p], wo0, ao[p]);
                ai[p] = ffma2(xv1[p], wi1, ai[p]);
                af[p] = ffma2(xv1[p], wf1, af[p]);
                ag[p] = ffma2(xv1[p], wg1, ag[p]);
                ao[p] = ffma2(xv1[p], wo1, ao[p]);
            }
        }
        mat_acc(&g_Whh[0][0][j], hs, ai, af, ag, ao);
        __syncwarp();
        cell_update(ai, af, ag, ao, bs[0], cst[0], &h_stage[wid][0][0][j]);
        __syncwarp();

        // ---------------- layers 1..3 ----------------
#pragma unroll 1
        for (int l = 1; l < NL; ++l) {
#pragma unroll
            for (int p = 0; p < NPAIR; ++p) { ai[p] = af[p] = ag[p] = ao[p] = 0ull; }
            mat_acc(&g_Wih[l - 1][0][j], hs + (l - 1) * NPAIR * H, ai, af, ag, ao); // input = h[l-1]
            mat_acc(&g_Whh[l][0][j],     hs + l * NPAIR * H,       ai, af, ag, ao); // recurrent
            __syncwarp();
            cell_update(ai, af, ag, ao, bs[l], cst[l], &h_stage[wid][l][0][j]);
            __syncwarp();
        }
    }

    // head: out[b] = sigmoid(h3[b] . Wlin + blin)
    float wl = g_Wlin[j];
    float s[BPW];
#pragma unroll
    for (int p = 0; p < NPAIR; ++p) {
        float2 hv = h_stage[wid][NL - 1][p][j];
        s[2 * p] = hv.x * wl;
        s[2 * p + 1] = hv.y * wl;
    }
#pragma unroll
    for (int q = 0; q < BPW; ++q)
#pragma unroll
        for (int off = 16; off > 0; off >>= 1)
            s[q] += __shfl_xor_sync(0xffffffffu, s[q], off);
    if (j == 0) {
        float bl = g_blin;
#pragma unroll
        for (int q = 0; q < BPW; ++q)
            out[base + q] = sigm(s[q] + bl);
    }
}

extern "C" void kernel_launch(void* const* d_in, const int* in_sizes, int n_in,
                              void* d_out, int out_size) {
    const float* x     = (const float*)d_in[0];
    const float* W_ih0 = (const float*)d_in[1];
    const float* W_ih  = (const float*)d_in[2];
    const float* W_hh  = (const float*)d_in[3];
    const float* b_ih  = (const float*)d_in[4];
    const float* b_hh  = (const float*)d_in[5];
    const float* W_lin = (const float*)d_in[6];
    const float* b_lin = (const float*)d_in[7];

    prep_kernel<<<64, 256>>>(W_ih0, W_ih, W_hh, b_ih, b_hh, W_lin, b_lin);

    int B = in_sizes[0] / (3 * TT);                  // 16384
    int blocks = B / (WARPS_CTA * BPW);              // 512
    lstm_kernel<<<blocks, THREADS>>>(x, (float*)d_out);
}